// round 1
// baseline (speedup 1.0000x reference)
#include <cuda_runtime.h>

typedef unsigned long long ull;

__device__ __forceinline__ ull fma2(ull a, ull b, ull c){
    ull d;
    asm("fma.rn.f32x2 %0, %1, %2, %3;" : "=l"(d) : "l"(a), "l"(b), "l"(c));
    return d;
}
__device__ __forceinline__ ull add2(ull a, ull b){
    ull d;
    asm("add.rn.f32x2 %0, %1, %2;" : "=l"(d) : "l"(a), "l"(b));
    return d;
}

// Problem constants (from reference): E=4 experts, D=128, G=16, KF=16, KTOP=2
// Features per row: 32 fourier (sin|cos) + 16 spline + 16 gauss + 16 wavelet = 80
// Output layout assumed: [embedding B*512][raw_weights B*4][mask B*4], float32.

__global__ __launch_bounds__(256, 1)
void mote_kernel(
    const float* __restrict__ timestamp,   // [B,1]
    const float* __restrict__ aux,         // [B,16]
    const float* __restrict__ router_W,    // [17,4]
    const float* __restrict__ router_b,    // [4]
    const float* __restrict__ freqs,       // [16]
    const float* __restrict__ fourier_W,   // [32,128]
    const float* __restrict__ knots,       // [16]
    const float* __restrict__ spline_W,    // [16,128]
    const float* __restrict__ centers,     // [16]
    const float* __restrict__ gauss_W,     // [16,128]
    const float* __restrict__ wav_centers, // [16]
    const float* __restrict__ wav_scales,  // [16]
    const float* __restrict__ wavelet_W,   // [16,128]
    float* __restrict__ out,
    int B)
{
    // Features for 32 rows, stored as duplicated float2 (v,v) so phase-2 FFMA2
    // reads the packed B-operand with one LDS.
    __shared__ __align__(16) float2 sFeat[32 * 80];
    __shared__ float4 sDisp[32];

    const int tid = threadIdx.x;
    const int c   = tid & 63;          // column pair: covers d = 2c, 2c+1

    // ---- Preload all expert weights into registers (lives whole kernel) ----
    ull wF[32], wS[16], wG[16], wW[16];
    {
        const ull* p = (const ull*)fourier_W;
        #pragma unroll
        for (int f = 0; f < 32; f++) wF[f] = p[f*64 + c];
        p = (const ull*)spline_W;
        #pragma unroll
        for (int f = 0; f < 16; f++) wS[f] = p[f*64 + c];
        p = (const ull*)gauss_W;
        #pragma unroll
        for (int f = 0; f < 16; f++) wG[f] = p[f*64 + c];
        p = (const ull*)wavelet_W;
        #pragma unroll
        for (int f = 0; f < 16; f++) wW[f] = p[f*64 + c];
    }

    const int s  = tid & 7;            // sub-thread within a row (phase 1)
    const int lr = tid >> 3;           // local row 0..31 (phase 1)
    const int rl = tid >> 6;           // row lane 0..3 (phase 2)
    const unsigned lane = tid & 31;
    const unsigned gb   = lane & 24;   // base lane of this 8-lane row group

    const size_t W_OFF = (size_t)B * 512;
    const size_t M_OFF = W_OFF + (size_t)B * 4;

    const int numBatches = B >> 5;     // 32 rows per batch
    for (int batch = blockIdx.x; batch < numBatches; batch += gridDim.x){
        const int rowBase = batch << 5;
        __syncthreads();               // sFeat/sDisp reuse fence

        // ================= Phase 1: router + features (8 thr/row) ==========
        {
            const int row = rowBase + lr;
            const float t = timestamp[row];

            float logit = -1e30f;
            if (s < 4){
                logit = router_b[s] + t * router_W[s];
                const float4* a4 = (const float4*)(aux + (size_t)row * 16);
                float4 x0 = a4[0], x1 = a4[1], x2 = a4[2], x3 = a4[3];
                logit += x0.x*router_W[ 4+s] + x0.y*router_W[ 8+s] + x0.z*router_W[12+s] + x0.w*router_W[16+s];
                logit += x1.x*router_W[20+s] + x1.y*router_W[24+s] + x1.z*router_W[28+s] + x1.w*router_W[32+s];
                logit += x2.x*router_W[36+s] + x2.y*router_W[40+s] + x2.z*router_W[44+s] + x2.w*router_W[48+s];
                logit += x3.x*router_W[52+s] + x3.y*router_W[56+s] + x3.z*router_W[60+s] + x3.w*router_W[64+s];
            }
            // gather all 4 logits of this row group
            float l0 = __shfl_sync(0xffffffffu, logit, gb + 0);
            float l1 = __shfl_sync(0xffffffffu, logit, gb + 1);
            float l2 = __shfl_sync(0xffffffffu, logit, gb + 2);
            float l3 = __shfl_sync(0xffffffffu, logit, gb + 3);
            float m  = fmaxf(fmaxf(l0, l1), fmaxf(l2, l3));
            float e0 = __expf(l0 - m), e1 = __expf(l1 - m);
            float e2 = __expf(l2 - m), e3 = __expf(l3 - m);
            float inv = __fdividef(1.0f, e0 + e1 + e2 + e3);
            float w0 = e0*inv, w1 = e1*inv, w2 = e2*inv, w3 = e3*inv;

            // top-2 ranks; ties break to lower index (match jax.lax.top_k)
            int r0 = (w1 >  w0) + (w2 >  w0) + (w3 >  w0);
            int r1 = (w0 >= w1) + (w2 >  w1) + (w3 >  w1);
            int r2 = (w0 >= w2) + (w1 >= w2) + (w3 >  w2);
            int r3 = (w0 >= w3) + (w1 >= w3) + (w2 >= w3);
            float d0 = (r0 < 2) ? w0 : 0.f;
            float d1 = (r1 < 2) ? w1 : 0.f;
            float d2 = (r2 < 2) ? w2 : 0.f;
            float d3 = (r3 < 2) ? w3 : 0.f;

            if (s == 0) sDisp[lr] = make_float4(d0, d1, d2, d3);
            if (s < 4){
                float ws = (s==0) ? w0 : (s==1) ? w1 : (s==2) ? w2 : w3;
                int   rs = (s==0) ? r0 : (s==1) ? r1 : (s==2) ? r2 : r3;
                out[W_OFF + (size_t)row*4 + s] = ws;
                out[M_OFF + (size_t)row*4 + s] = (rs < 2) ? 1.0f : 0.0f;
            }

            // 80 features, pre-scaled by dispatch; j = s + 8k stays within one
            // 16-wide category for each compile-time k -> uniform branches.
            #pragma unroll
            for (int k = 0; k < 10; k++){
                const int j = s + 8*k;
                float v, dd;
                if (k < 2)      { v = __sinf(t * freqs[j]);                       dd = d0; }
                else if (k < 4) { v = __cosf(t * freqs[j - 16]);                  dd = d0; }
                else if (k < 6) { float u = (t - knots[j - 32]) * 3.75f;          v = __expf(-u*u);              dd = d1; }
                else if (k < 8) { float u =  t - centers[j - 48];                 v = __expf(-u*u);              dd = d2; }
                else            { float u = __fdividef(t - wav_centers[j - 64], wav_scales[j - 64]);
                                  v = (1.f - u*u) * __expf(-0.5f*u*u);            dd = d3; }
                float vv = v * dd;
                sFeat[lr*80 + j] = make_float2(vv, vv);
            }
        }
        __syncthreads();

        // ================= Phase 2: matvecs, warp == one row ================
        #pragma unroll 1
        for (int rg = 0; rg < 8; rg++){
            const int lrow = (rg << 2) + rl;
            const int row  = rowBase + lrow;
            const float4 dsp = sDisp[lrow];
            const float2* feat = &sFeat[lrow * 80];
            ull* outRow = (ull*)out + (size_t)row * 256 + c;

            // expert 0: fourier (32 features)
            if (dsp.x != 0.f){
                ull a0 = 0, a1 = 0;
                #pragma unroll
                for (int f = 0; f < 32; f += 2){
                    ulonglong2 ft = *(const ulonglong2*)(feat + f);
                    a0 = fma2(wF[f],   ft.x, a0);
                    a1 = fma2(wF[f+1], ft.y, a1);
                }
                outRow[0] = add2(a0, a1);
            } else outRow[0] = 0ull;

            // expert 1: spline
            if (dsp.y != 0.f){
                ull a0 = 0, a1 = 0;
                #pragma unroll
                for (int f = 0; f < 16; f += 2){
                    ulonglong2 ft = *(const ulonglong2*)(feat + 32 + f);
                    a0 = fma2(wS[f],   ft.x, a0);
                    a1 = fma2(wS[f+1], ft.y, a1);
                }
                outRow[64] = add2(a0, a1);
            } else outRow[64] = 0ull;

            // expert 2: gauss
            if (dsp.z != 0.f){
                ull a0 = 0, a1 = 0;
                #pragma unroll
                for (int f = 0; f < 16; f += 2){
                    ulonglong2 ft = *(const ulonglong2*)(feat + 48 + f);
                    a0 = fma2(wG[f],   ft.x, a0);
                    a1 = fma2(wG[f+1], ft.y, a1);
                }
                outRow[128] = add2(a0, a1);
            } else outRow[128] = 0ull;

            // expert 3: wavelet
            if (dsp.w != 0.f){
                ull a0 = 0, a1 = 0;
                #pragma unroll
                for (int f = 0; f < 16; f += 2){
                    ulonglong2 ft = *(const ulonglong2*)(feat + 64 + f);
                    a0 = fma2(wW[f],   ft.x, a0);
                    a1 = fma2(wW[f+1], ft.y, a1);
                }
                outRow[192] = add2(a0, a1);
            } else outRow[192] = 0ull;
        }
    }
}

extern "C" void kernel_launch(void* const* d_in, const int* in_sizes, int n_in,
                              void* d_out, int out_size)
{
    const float* timestamp   = (const float*)d_in[0];
    const float* aux         = (const float*)d_in[1];
    const float* router_W    = (const float*)d_in[2];
    const float* router_b    = (const float*)d_in[3];
    const float* freqs       = (const float*)d_in[4];
    const float* fourier_W   = (const float*)d_in[5];
    const float* knots       = (const float*)d_in[6];
    const float* spline_W    = (const float*)d_in[7];
    const float* centers     = (const float*)d_in[8];
    const float* gauss_W     = (const float*)d_in[9];
    const float* wav_centers = (const float*)d_in[10];
    const float* wav_scales  = (const float*)d_in[11];
    const float* wavelet_W   = (const float*)d_in[12];
    float* out = (float*)d_out;

    const int B = in_sizes[0];   // timestamp is [B,1]

    mote_kernel<<<148, 256>>>(timestamp, aux, router_W, router_b, freqs,
                              fourier_W, knots, spline_W, centers, gauss_W,
                              wav_centers, wav_scales, wavelet_W, out, B);
}